// round 8
// baseline (speedup 1.0000x reference)
#include <cuda_runtime.h>

#define BB    16
#define NN    16384
#define NFPS  512
#define NREG  50
#define TOPK  4
#define NB    128
#define R2C   0.16f

typedef unsigned int u32;
typedef unsigned long long u64;

__device__ int g_fps_idx[BB][NFPS];
__device__ int g_counts[BB][NREG];
__device__ int g_top4[BB][TOPK];

// ---- packed f32x2 helpers (sm_100a) ---------------------------------------
__device__ __forceinline__ u64 pack2(float lo, float hi) {
    u64 r; asm("mov.b64 %0,{%1,%2};" : "=l"(r) : "f"(lo), "f"(hi)); return r;
}
__device__ __forceinline__ void unpack2(u64 v, float& lo, float& hi) {
    asm("mov.b64 {%0,%1},%2;" : "=f"(lo), "=f"(hi) : "l"(v));
}
__device__ __forceinline__ u64 add2(u64 a, u64 b) {
    u64 r; asm("add.rn.f32x2 %0,%1,%2;" : "=l"(r) : "l"(a), "l"(b)); return r;
}
__device__ __forceinline__ u64 mul2(u64 a, u64 b) {
    u64 r; asm("mul.rn.f32x2 %0,%1,%2;" : "=l"(r) : "l"(a), "l"(b)); return r;
}
__device__ __forceinline__ u64 fma2(u64 a, u64 b, u64 c) {
    u64 r; asm("fma.rn.f32x2 %0,%1,%2,%3;" : "=l"(r) : "l"(a), "l"(b), "l"(c)); return r;
}

// ---- cluster / mbarrier helpers --------------------------------------------
__device__ __forceinline__ u32 smem_u32(const void* p) {
    return (u32)__cvta_generic_to_shared(p);
}
__device__ __forceinline__ u32 mapa_rank(u32 addr, u32 rank) {
    u32 r;
    asm("mapa.shared::cluster.u32 %0,%1,%2;" : "=r"(r) : "r"(addr), "r"(rank));
    return r;
}
__device__ __forceinline__ void st_cluster_b64(u32 addr, u64 v) {
    asm volatile("st.shared::cluster.b64 [%0],%1;" :: "r"(addr), "l"(v) : "memory");
}
__device__ __forceinline__ void mbar_init(u32 addr, u32 cnt) {
    asm volatile("mbarrier.init.shared.b64 [%0],%1;" :: "r"(addr), "r"(cnt) : "memory");
}
__device__ __forceinline__ void mbar_arrive_local(u32 addr) {
    asm volatile("mbarrier.arrive.release.cta.shared::cta.b64 _,[%0];" :: "r"(addr) : "memory");
}
__device__ __forceinline__ void mbar_arrive_remote(u32 remote_addr) {
    asm volatile("mbarrier.arrive.release.cluster.shared::cluster.b64 _,[%0];"
                 :: "r"(remote_addr) : "memory");
}
__device__ __forceinline__ void mbar_wait(u32 addr, u32 parity) {
    asm volatile(
        "{\n\t.reg .pred P;\n\t"
        "WL_%=:\n\t"
        "mbarrier.try_wait.parity.acquire.cluster.shared::cta.b64 P,[%0],%1,0x989680;\n\t"
        "@P bra.uni WD_%=;\n\t"
        "bra.uni WL_%=;\n\t"
        "WD_%=:\n\t}"
        :: "r"(addr), "r"(parity) : "memory");
}
#define CLUSTER_SYNC() do {                                          \
    asm volatile("barrier.cluster.arrive.aligned;" ::: "memory");    \
    asm volatile("barrier.cluster.wait.aligned;" ::: "memory");      \
} while (0)

// ============================================================================
// Kernel 1: FPS, cluster of 2 CTAs per batch; 8192 pts/CTA, 16/thread,
// coordinates fully register-resident.  ONE-PHASE exchange: each warp's
// owner lane (warp argmax by (dist, rev-idx) redux) extracts its candidate
// {key, xy, z} from registers and stores it to the SAME slot [gw = rank*16
// + warp] in BOTH CTAs' smem (local store + 3 st.shared::cluster), then
// release-arrives on both mbarriers.  mbar count = 32 (16 local + 16
// remote).  No __syncthreads in the loop — one mbar parity wait, then every
// thread scans all 32 keys and reads the winner's coords from smem.
// Key = (dist_bits<<32)|(16383-idx): bit-exact vs jnp.argmax tie rule.
// ============================================================================
#define CSZ   2
#define LPTS  (NN / CSZ)     /* 8192 */
#define FT    512
#define NW    (FT / 32)      /* 16 */
#define FPPT  (LPTS / FT)    /* 16 */

__global__ void __launch_bounds__(FT, 1) __cluster_dims__(CSZ, 1, 1)
fps_kernel(const float* __restrict__ pts, float* __restrict__ out)
{
    __shared__ __align__(16) u64 s_keys[2][2 * NW];       // [par][gw]
    __shared__ __align__(16) u64 s_cxyz[2][2 * NW][2];    // [par][gw]{xy, z}
    __shared__ __align__(8)  u64 s_mbar[1];
    __shared__ float4 s_hist[NFPS];

    const int rank = blockIdx.x, b = blockIdx.y, t = threadIdx.x;
    const int warp = t >> 5;
    const float* base = pts + (size_t)b * 3 * NN;
    const int g0 = rank * LPTS;
    const u32 mbar_a = smem_u32(&s_mbar[0]);
    const u32 peer = (u32)(rank ^ 1);
    const int gw = rank * NW + warp;

    if (t == 0) mbar_init(mbar_a, 2 * NW);
    __syncthreads();
    CLUSTER_SYNC();   // peer mbar init visible before any remote arrive

    // my 8192 points in registers, packed pairs (slots 2j, 2j+1)
    u64 rx[FPPT / 2], ry[FPPT / 2], rz[FPPT / 2];
#pragma unroll
    for (int j = 0; j < FPPT / 2; j++) {
        const int n0 = g0 + t + (2 * j) * FT, n1 = n0 + FT;
        rx[j] = pack2(base[n0], base[n1]);
        ry[j] = pack2(base[NN + n0], base[NN + n1]);
        rz[j] = pack2(base[2 * NN + n0], base[2 * NN + n1]);
    }
    float dist[FPPT];
#pragma unroll
    for (int k = 0; k < FPPT; k++) dist[k] = 1e10f;

    float cx = base[0], cy = base[NN], cz = base[2 * NN];
    int cur = 0;

    for (int i = 0; i < NFPS; i++) {
        if (rank == 0 && t == 0)
            s_hist[i] = make_float4(cx, cy, cz, __int_as_float(cur));

        const u64 nx = pack2(-cx, -cx), ny = pack2(-cy, -cy), nz = pack2(-cz, -cz);
        float v0 = -1.0f, v1 = -1.0f;
#pragma unroll
        for (int j = 0; j < FPPT / 2; j++) {
            u64 dx = add2(rx[j], nx), dy = add2(ry[j], ny), dz = add2(rz[j], nz);
            u64 s = mul2(dx, dx); s = fma2(dy, dy, s); s = fma2(dz, dz, s);
            float a, c; unpack2(s, a, c);
            float d0 = fminf(dist[2 * j], a), d1 = fminf(dist[2 * j + 1], c);
            dist[2 * j] = d0; dist[2 * j + 1] = d1;
            v0 = fmaxf(v0, d0); v1 = fmaxf(v1, d1);
        }
        const float vmax = fmaxf(v0, v1);
        const int par = i & 1;

        // warp argmax: max dist bits, then max reversed index among matchers
        const u32 wm = __reduce_max_sync(0xffffffffu, __float_as_uint(vmax));
        u32 rev = 0u;
        int k0 = -1;
        if (__float_as_uint(vmax) == wm) {
#pragma unroll
            for (int k = 0; k < FPPT; k++)
                if (k0 < 0 && __float_as_uint(dist[k]) == wm) k0 = k;
            rev = 16383u - (u32)(g0 + t + k0 * FT);   // first match = smallest idx
        }
        const u32 wrev = __reduce_max_sync(0xffffffffu, rev);

        if (k0 >= 0 && rev == wrev) {
            // owner lane of this warp: extract coords, publish to BOTH CTAs
            const int jj = k0 >> 1, hi = k0 & 1;
            float wx = 0.f, wy = 0.f, wz = 0.f;
#pragma unroll
            for (int j = 0; j < FPPT / 2; j++) {
                if (j == jj) {
                    float a, c;
                    unpack2(rx[j], a, c); wx = hi ? c : a;
                    unpack2(ry[j], a, c); wy = hi ? c : a;
                    unpack2(rz[j], a, c); wz = hi ? c : a;
                }
            }
            const u64 key = ((u64)wm << 32) | (u64)wrev;
            const u64 xy = (u64)__float_as_uint(wx) | ((u64)__float_as_uint(wy) << 32);
            const u64 zz = (u64)__float_as_uint(wz);
            s_keys[par][gw] = key;
            s_cxyz[par][gw][0] = xy;
            s_cxyz[par][gw][1] = zz;
            st_cluster_b64(mapa_rank(smem_u32(&s_keys[par][gw]), peer), key);
            st_cluster_b64(mapa_rank(smem_u32(&s_cxyz[par][gw][0]), peer), xy);
            st_cluster_b64(mapa_rank(smem_u32(&s_cxyz[par][gw][1]), peer), zz);
            mbar_arrive_local(mbar_a);
            mbar_arrive_remote(mapa_rank(mbar_a, peer));
        }

        mbar_wait(mbar_a, (u32)par);          // all 32 candidates visible

        // global argmax over 32 unique keys
        u64 bk = s_keys[par][0];
        int bi = 0;
#pragma unroll
        for (int w = 1; w < 2 * NW; w++) {
            const u64 k = s_keys[par][w];
            if (k > bk) { bk = k; bi = w; }
        }
        float a, c;
        unpack2(s_cxyz[par][bi][0], a, c);
        cx = a; cy = c;
        cz = __uint_as_float((u32)s_cxyz[par][bi][1]);
        cur = 16383 - (int)(bk & 0xffffffffu);
    }

    if (rank == 0) {
        __syncthreads();
        if (t < NFPS) {
            const float4 h = s_hist[t];
            const int idx = __float_as_int(h.w);
            g_fps_idx[b][t] = idx;
            float* o = out + ((size_t)b * 1536 + 1024 + t) * 3;
            o[0] = h.x; o[1] = h.y; o[2] = h.z;
        }
    }
    CLUSTER_SYNC();   // no CTA exits while peer stores may be in flight
}

// ============================================================================
// Kernel 2: per-(batch, anchor) ball count.  grid = (NREG, BB)
// ============================================================================
__global__ void count_kernel(const float* __restrict__ pts)
{
    const int a = blockIdx.x, b = blockIdx.y;
    const int t = threadIdx.x;
    const float* base = pts + (size_t)b * 3 * NN;
    const int aidx = g_fps_idx[b][a];
    const float ax = base[aidx], ay = base[NN + aidx], az = base[2 * NN + aidx];
    const float a2 = ax * ax + ay * ay + az * az;

    int cnt = 0;
    for (int n = t; n < NN; n += 256) {
        float x = base[n], y = base[NN + n], z = base[2 * NN + n];
        float dot = ax * x + ay * y + az * z;
        float p2 = x * x + y * y + z * z;
        float d = (-2.0f * dot + a2) + p2;
        cnt += (d < R2C) ? 1 : 0;
    }
    __shared__ int s_c[8];
#pragma unroll
    for (int o = 16; o > 0; o >>= 1) cnt += __shfl_xor_sync(0xffffffffu, cnt, o);
    if ((t & 31) == 0) s_c[t >> 5] = cnt;
    __syncthreads();
    if (t == 0) {
        int s = 0;
#pragma unroll
        for (int w = 0; w < 8; w++) s += s_c[w];
        g_counts[b][a] = min(s, 1000);
    }
}

// ============================================================================
// Kernel 3: top-4 anchors by count (ties -> lower index).  grid = BB
// ============================================================================
__global__ void top4_kernel()
{
    const int b = blockIdx.x;
    if (threadIdx.x != 0) return;
    int cnts[NREG];
    for (int a = 0; a < NREG; a++) cnts[a] = g_counts[b][a];
    for (int j = 0; j < TOPK; j++) {
        int best = -1, bi = 0;
        for (int a = 0; a < NREG; a++)
            if (cnts[a] > best) { best = cnts[a]; bi = a; }
        g_top4[b][j] = g_fps_idx[b][bi];
        cnts[bi] = -2;
    }
}

// ============================================================================
// Kernel 4: 128-NN per (query, batch).  grid = (TOPK, BB)  (round-2, 54us)
// ============================================================================
#define KT   512
#define KPPT 32

__global__ void __launch_bounds__(KT, 1)
knn_kernel(const float* __restrict__ pts, float* __restrict__ out)
{
    const int q = blockIdx.x, b = blockIdx.y;
    const int t = threadIdx.x, lane = t & 31, warp = t >> 5;
    const float* base = pts + (size_t)b * 3 * NN;
    __shared__ u32 s_wmin[KT / 32];
    __shared__ u32 s_minv;
    __shared__ int s_tid[2];
    __shared__ int s_win[NB];

    if (t == 0) { s_tid[0] = 0x7fffffff; s_tid[1] = 0x7fffffff; }

    const int qidx = g_top4[b][q];
    const float qx = base[qidx], qy = base[NN + qidx], qz = base[2 * NN + qidx];
    const float q2 = qx * qx + qy * qy + qz * qz;

    const int p0 = t * KPPT;
    u32 u[KPPT];

#define DPT(X, Y, Z, K) {                                                   \
        float dot = qx * (X) + qy * (Y) + qz * (Z);                         \
        float p2 = (X) * (X) + (Y) * (Y) + (Z) * (Z);                       \
        float d = (-2.0f * dot + q2) + p2;                                  \
        u32 ub = __float_as_uint(d);                                        \
        ub = (ub & 0x80000000u) ? ~ub : (ub | 0x80000000u);                 \
        u[K] = ub; }

#pragma unroll
    for (int g = 0; g < 8; g++) {
        const float4 x4 = *(const float4*)&base[p0 + 4 * g];
        const float4 y4 = *(const float4*)&base[NN + p0 + 4 * g];
        const float4 z4 = *(const float4*)&base[2 * NN + p0 + 4 * g];
        DPT(x4.x, y4.x, z4.x, 4 * g + 0)
        DPT(x4.y, y4.y, z4.y, 4 * g + 1)
        DPT(x4.z, y4.z, z4.z, 4 * g + 2)
        DPT(x4.w, y4.w, z4.w, 4 * g + 3)
    }
#undef DPT

    u32 gmin[4];
#pragma unroll
    for (int g = 0; g < 4; g++) {
        u32 m = u[8 * g];
#pragma unroll
        for (int k = 1; k < 8; k++) m = min(m, u[8 * g + k]);
        gmin[g] = m;
    }
    u32 tmin = min(min(gmin[0], gmin[1]), min(gmin[2], gmin[3]));
    __syncthreads();

    for (int j = 0; j < NB; j++) {
        u32 wm = __reduce_min_sync(0xffffffffu, tmin);
        if (lane == 0) s_wmin[warp] = wm;
        __syncthreads();
        if (warp == 0) {
            u32 v = (lane < KT / 32) ? s_wmin[lane] : 0xffffffffu;
            v = __reduce_min_sync(0xffffffffu, v);
            if (lane == 0) s_minv = v;
        }
        __syncthreads();
        const u32 m = s_minv;
        const int slot = j & 1;
        if (tmin == m) atomicMin(&s_tid[slot], t);
        if (t == 0) s_tid[slot ^ 1] = 0x7fffffff;
        __syncthreads();
        if (t == s_tid[slot]) {
            bool found = false;
#pragma unroll
            for (int g = 0; g < 4; g++) {
                if (!found && gmin[g] == m) {
                    bool f2 = false;
#pragma unroll
                    for (int k = 0; k < 8; k++) {
                        if (!f2 && u[8 * g + k] == m) {
                            u[8 * g + k] = 0xffffffffu;
                            s_win[j] = p0 + 8 * g + k;
                            f2 = true;
                        }
                    }
                    u32 nm = u[8 * g];
#pragma unroll
                    for (int k = 1; k < 8; k++) nm = min(nm, u[8 * g + k]);
                    gmin[g] = nm;
                    found = true;
                }
            }
            tmin = min(min(gmin[0], gmin[1]), min(gmin[2], gmin[3]));
        }
    }

    __syncthreads();
    if (t < NB) {
        const int win = s_win[t];
        const float x = base[win], y = base[NN + win], z = base[2 * NN + win];
        const size_t r = (size_t)b * 1536 + (size_t)q * NB + t;
        float* o1 = out + r * 3;
        o1[0] = x; o1[1] = y; o1[2] = z;
        float* o2 = out + (r + 512) * 3;
        o2[0] = x; o2[1] = y; o2[2] = z;
    }
}

// ============================================================================
extern "C" void kernel_launch(void* const* d_in, const int* in_sizes, int n_in,
                              void* d_out, int out_size)
{
    const float* pts = (const float*)d_in[0];
    float* out = (float*)d_out;

    fps_kernel<<<dim3(CSZ, BB), FT>>>(pts, out);
    count_kernel<<<dim3(NREG, BB), 256>>>(pts);
    top4_kernel<<<BB, 32>>>();
    knn_kernel<<<dim3(TOPK, BB), KT>>>(pts, out);
}

// round 9
// speedup vs baseline: 1.9254x; 1.9254x over previous
#include <cuda_runtime.h>

#define BB    16
#define NN    16384
#define NFPS  512
#define NANC  50
#define NREG  50
#define TOPK  4
#define NB    128
#define R2C   0.16f

typedef unsigned int u32;
typedef unsigned long long u64;

__device__ int g_fps_idx[BB][NREG];
__device__ int g_counts[BB][NREG];
__device__ int g_top4[BB][TOPK];

// ---- packed f32x2 helpers (sm_100a) ---------------------------------------
__device__ __forceinline__ u64 pack2(float lo, float hi) {
    u64 r; asm("mov.b64 %0,{%1,%2};" : "=l"(r) : "f"(lo), "f"(hi)); return r;
}
__device__ __forceinline__ void unpack2(u64 v, float& lo, float& hi) {
    asm("mov.b64 {%0,%1},%2;" : "=f"(lo), "=f"(hi) : "l"(v));
}
__device__ __forceinline__ u64 add2(u64 a, u64 b) {
    u64 r; asm("add.rn.f32x2 %0,%1,%2;" : "=l"(r) : "l"(a), "l"(b)); return r;
}
__device__ __forceinline__ u64 mul2(u64 a, u64 b) {
    u64 r; asm("mul.rn.f32x2 %0,%1,%2;" : "=l"(r) : "l"(a), "l"(b)); return r;
}
__device__ __forceinline__ u64 fma2(u64 a, u64 b, u64 c) {
    u64 r; asm("fma.rn.f32x2 %0,%1,%2,%3;" : "=l"(r) : "l"(a), "l"(b), "l"(c)); return r;
}

// ---- cluster / mbarrier helpers --------------------------------------------
__device__ __forceinline__ u32 smem_u32(const void* p) {
    return (u32)__cvta_generic_to_shared(p);
}
__device__ __forceinline__ u32 mapa_rank(u32 addr, u32 rank) {
    u32 r;
    asm("mapa.shared::cluster.u32 %0,%1,%2;" : "=r"(r) : "r"(addr), "r"(rank));
    return r;
}
__device__ __forceinline__ void st_cluster_b64(u32 addr, u64 v) {
    asm volatile("st.shared::cluster.b64 [%0],%1;" :: "r"(addr), "l"(v) : "memory");
}
__device__ __forceinline__ void mbar_init(u32 addr, u32 cnt) {
    asm volatile("mbarrier.init.shared.b64 [%0],%1;" :: "r"(addr), "r"(cnt) : "memory");
}
__device__ __forceinline__ void mbar_arrive_local(u32 addr) {
    asm volatile("mbarrier.arrive.release.cta.shared::cta.b64 _,[%0];" :: "r"(addr) : "memory");
}
__device__ __forceinline__ void mbar_arrive_remote(u32 remote_addr) {
    asm volatile("mbarrier.arrive.release.cluster.shared::cluster.b64 _,[%0];"
                 :: "r"(remote_addr) : "memory");
}
__device__ __forceinline__ void mbar_wait(u32 addr, u32 parity) {
    asm volatile(
        "{\n\t.reg .pred P;\n\t"
        "WL_%=:\n\t"
        "mbarrier.try_wait.parity.acquire.cluster.shared::cta.b64 P,[%0],%1,0x989680;\n\t"
        "@P bra.uni WD_%=;\n\t"
        "bra.uni WL_%=;\n\t"
        "WD_%=:\n\t}"
        :: "r"(addr), "r"(parity) : "memory");
}
#define CLUSTER_SYNC() do {                                          \
    asm volatile("barrier.cluster.arrive.aligned;" ::: "memory");    \
    asm volatile("barrier.cluster.wait.aligned;" ::: "memory");      \
} while (0)

// ============================================================================
// FPS (validated round-5 structure), cluster of 2 CTAs per batch; 8192
// pts/CTA, 16/thread, coordinates fully register-resident.
// Template: NIT iterations; MAIN=true writes out rows [1024,1536) only,
// MAIN=false writes g_fps_idx[b][0..NIT) only (anchor prefix — identical
// deterministic computation, so the prefix matches the full run exactly).
// ============================================================================
#define CSZ   2
#define LPTS  (NN / CSZ)     /* 8192 */
#define FT    512
#define FPPT  (LPTS / FT)    /* 16 */

template<int NIT, bool MAIN>
__global__ void __launch_bounds__(FT, 1) __cluster_dims__(CSZ, 1, 1)
fps_kernel(const float* __restrict__ pts, float* __restrict__ out)
{
    __shared__ __align__(16) u32 s_wmax[16];
    __shared__ int  s_widx[2];
    __shared__ u64  s_cand[2][CSZ][3];     // [slot][rank]{key, xy, z}
    __shared__ __align__(8) u64 s_mbar[1];
    __shared__ float4 s_hist[NIT];

    const int rank = blockIdx.x, b = blockIdx.y, t = threadIdx.x;
    const int lane = t & 31, warp = t >> 5;
    const float* base = pts + (size_t)b * 3 * NN;
    const int g0 = rank * LPTS;
    const u32 mbar_a = smem_u32(&s_mbar[0]);
    const u32 peer = (u32)(rank ^ 1);

    if (t == 0) {
        s_widx[0] = 0x7fffffff;
        s_widx[1] = 0x7fffffff;
        mbar_init(mbar_a, 2);
    }
    __syncthreads();
    CLUSTER_SYNC();   // peer mbar init visible before any remote arrive

    // my 8192 points in registers, packed pairs (slots 2j, 2j+1)
    u64 rx[FPPT / 2], ry[FPPT / 2], rz[FPPT / 2];
#pragma unroll
    for (int j = 0; j < FPPT / 2; j++) {
        const int n0 = g0 + t + (2 * j) * FT, n1 = n0 + FT;
        rx[j] = pack2(base[n0], base[n1]);
        ry[j] = pack2(base[NN + n0], base[NN + n1]);
        rz[j] = pack2(base[2 * NN + n0], base[2 * NN + n1]);
    }
    float dist[FPPT];
#pragma unroll
    for (int k = 0; k < FPPT; k++) dist[k] = 1e10f;

    float cx = base[0], cy = base[NN], cz = base[2 * NN];
    int cur = 0;

    for (int i = 0; i < NIT; i++) {
        if (rank == 0 && t == 0)
            s_hist[i] = make_float4(cx, cy, cz, __int_as_float(cur));

        const u64 nx = pack2(-cx, -cx), ny = pack2(-cy, -cy), nz = pack2(-cz, -cz);
        float v0 = -1.0f, v1 = -1.0f;
#pragma unroll
        for (int j = 0; j < FPPT / 2; j++) {
            u64 dx = add2(rx[j], nx), dy = add2(ry[j], ny), dz = add2(rz[j], nz);
            u64 s = mul2(dx, dx); s = fma2(dy, dy, s); s = fma2(dz, dz, s);
            float a, c; unpack2(s, a, c);
            float d0 = fminf(dist[2 * j], a), d1 = fminf(dist[2 * j + 1], c);
            dist[2 * j] = d0; dist[2 * j + 1] = d1;
            v0 = fmaxf(v0, d0); v1 = fmaxf(v1, d1);
        }
        const float vmax = fmaxf(v0, v1);

        const u32 wm = __reduce_max_sync(0xffffffffu, __float_as_uint(vmax));
        if (lane == 0) s_wmax[warp] = wm;
        __syncthreads();                             // (1)
        const int slot = i & 1;
        if (t == 0) s_widx[slot ^ 1] = 0x7fffffff;

        // flat block max: broadcast reads of 16 warp maxes
        const uint4 q0 = *(const uint4*)&s_wmax[0];
        const uint4 q1 = *(const uint4*)&s_wmax[4];
        const uint4 q2 = *(const uint4*)&s_wmax[8];
        const uint4 q3 = *(const uint4*)&s_wmax[12];
        u32 m = max(max(max(q0.x, q0.y), max(q0.z, q0.w)),
                    max(max(q1.x, q1.y), max(q1.z, q1.w)));
        m = max(m, max(max(max(q2.x, q2.y), max(q2.z, q2.w)),
                       max(max(q3.x, q3.y), max(q3.z, q3.w))));

        if (__float_as_uint(vmax) == m) {
#pragma unroll
            for (int k = 0; k < FPPT; k++)
                if (__float_as_uint(dist[k]) == m)
                    atomicMin(&s_widx[slot], g0 + t + k * FT);
        }
        __syncthreads();                             // (2)
        const int widx = s_widx[slot];

        const int mine = widx - g0 - t;
        if (mine >= 0 && mine < LPTS && (mine & (FT - 1)) == 0) {
            // I own the local winner: extract coords from my registers
            const int k = mine >> 9, j = k >> 1, hi = k & 1;
            float wx = 0.f, wy = 0.f, wz = 0.f;
#pragma unroll
            for (int jj = 0; jj < FPPT / 2; jj++) {
                if (jj == j) {
                    float a, c;
                    unpack2(rx[jj], a, c); wx = hi ? c : a;
                    unpack2(ry[jj], a, c); wy = hi ? c : a;
                    unpack2(rz[jj], a, c); wz = hi ? c : a;
                }
            }
            const u64 key = ((u64)m << 14) | (u64)(16383u - (u32)widx);
            const u64 xy = (u64)__float_as_uint(wx) | ((u64)__float_as_uint(wy) << 32);
            const u64 zz = (u64)__float_as_uint(wz);
            s_cand[slot][rank][0] = key;
            s_cand[slot][rank][1] = xy;
            s_cand[slot][rank][2] = zz;
            const u32 ra = mapa_rank(smem_u32(&s_cand[slot][rank][0]), peer);
            st_cluster_b64(ra, key);
            st_cluster_b64(ra + 8, xy);
            st_cluster_b64(ra + 16, zz);
            mbar_arrive_local(mbar_a);
            mbar_arrive_remote(mapa_rank(mbar_a, peer));
        }

        mbar_wait(mbar_a, (u32)(i & 1));             // both candidates visible

        const u64 k0 = s_cand[slot][0][0], k1 = s_cand[slot][1][0];
        const int w = (k1 > k0) ? 1 : 0;
        const u64 kw = w ? k1 : k0;
        float a, c;
        unpack2(s_cand[slot][w][1], a, c);
        cx = a; cy = c;
        cz = __uint_as_float((u32)s_cand[slot][w][2]);
        cur = 16383 - (int)(kw & 0x3FFFu);
    }

    if (rank == 0) {
        __syncthreads();
        if (MAIN) {
            if (t < NIT) {
                const float4 h = s_hist[t];
                float* o = out + ((size_t)b * 1536 + 1024 + t) * 3;
                o[0] = h.x; o[1] = h.y; o[2] = h.z;
            }
        } else {
            if (t < NIT)
                g_fps_idx[b][t] = __float_as_int(s_hist[t].w);
        }
    }
    CLUSTER_SYNC();   // no CTA exits while peer stores may be in flight
}

// ============================================================================
// Kernel 2: per-(batch, anchor) ball count.  grid = (NREG, BB)
// ============================================================================
__global__ void count_kernel(const float* __restrict__ pts)
{
    const int a = blockIdx.x, b = blockIdx.y;
    const int t = threadIdx.x;
    const float* base = pts + (size_t)b * 3 * NN;
    const int aidx = g_fps_idx[b][a];
    const float ax = base[aidx], ay = base[NN + aidx], az = base[2 * NN + aidx];
    const float a2 = ax * ax + ay * ay + az * az;

    int cnt = 0;
    for (int n = t; n < NN; n += 256) {
        float x = base[n], y = base[NN + n], z = base[2 * NN + n];
        float dot = ax * x + ay * y + az * z;
        float p2 = x * x + y * y + z * z;
        float d = (-2.0f * dot + a2) + p2;
        cnt += (d < R2C) ? 1 : 0;
    }
    __shared__ int s_c[8];
#pragma unroll
    for (int o = 16; o > 0; o >>= 1) cnt += __shfl_xor_sync(0xffffffffu, cnt, o);
    if ((t & 31) == 0) s_c[t >> 5] = cnt;
    __syncthreads();
    if (t == 0) {
        int s = 0;
#pragma unroll
        for (int w = 0; w < 8; w++) s += s_c[w];
        g_counts[b][a] = min(s, 1000);
    }
}

// ============================================================================
// Kernel 3: top-4 anchors by count (ties -> lower index).  grid = BB
// ============================================================================
__global__ void top4_kernel()
{
    const int b = blockIdx.x;
    if (threadIdx.x != 0) return;
    int cnts[NREG];
    for (int a = 0; a < NREG; a++) cnts[a] = g_counts[b][a];
    for (int j = 0; j < TOPK; j++) {
        int best = -1, bi = 0;
        for (int a = 0; a < NREG; a++)
            if (cnts[a] > best) { best = cnts[a]; bi = a; }
        g_top4[b][j] = g_fps_idx[b][bi];
        cnts[bi] = -2;
    }
}

// ============================================================================
// Kernel 4: 128-NN per (query, batch).  grid = (TOPK, BB)  (validated, 54us)
// ============================================================================
#define KT   512
#define KPPT 32

__global__ void __launch_bounds__(KT, 1)
knn_kernel(const float* __restrict__ pts, float* __restrict__ out)
{
    const int q = blockIdx.x, b = blockIdx.y;
    const int t = threadIdx.x, lane = t & 31, warp = t >> 5;
    const float* base = pts + (size_t)b * 3 * NN;
    __shared__ u32 s_wmin[KT / 32];
    __shared__ u32 s_minv;
    __shared__ int s_tid[2];
    __shared__ int s_win[NB];

    if (t == 0) { s_tid[0] = 0x7fffffff; s_tid[1] = 0x7fffffff; }

    const int qidx = g_top4[b][q];
    const float qx = base[qidx], qy = base[NN + qidx], qz = base[2 * NN + qidx];
    const float q2 = qx * qx + qy * qy + qz * qz;

    const int p0 = t * KPPT;
    u32 u[KPPT];

#define DPT(X, Y, Z, K) {                                                   \
        float dot = qx * (X) + qy * (Y) + qz * (Z);                         \
        float p2 = (X) * (X) + (Y) * (Y) + (Z) * (Z);                       \
        float d = (-2.0f * dot + q2) + p2;                                  \
        u32 ub = __float_as_uint(d);                                        \
        ub = (ub & 0x80000000u) ? ~ub : (ub | 0x80000000u);                 \
        u[K] = ub; }

#pragma unroll
    for (int g = 0; g < 8; g++) {
        const float4 x4 = *(const float4*)&base[p0 + 4 * g];
        const float4 y4 = *(const float4*)&base[NN + p0 + 4 * g];
        const float4 z4 = *(const float4*)&base[2 * NN + p0 + 4 * g];
        DPT(x4.x, y4.x, z4.x, 4 * g + 0)
        DPT(x4.y, y4.y, z4.y, 4 * g + 1)
        DPT(x4.z, y4.z, z4.z, 4 * g + 2)
        DPT(x4.w, y4.w, z4.w, 4 * g + 3)
    }
#undef DPT

    u32 gmin[4];
#pragma unroll
    for (int g = 0; g < 4; g++) {
        u32 m = u[8 * g];
#pragma unroll
        for (int k = 1; k < 8; k++) m = min(m, u[8 * g + k]);
        gmin[g] = m;
    }
    u32 tmin = min(min(gmin[0], gmin[1]), min(gmin[2], gmin[3]));
    __syncthreads();

    for (int j = 0; j < NB; j++) {
        u32 wm = __reduce_min_sync(0xffffffffu, tmin);
        if (lane == 0) s_wmin[warp] = wm;
        __syncthreads();
        if (warp == 0) {
            u32 v = (lane < KT / 32) ? s_wmin[lane] : 0xffffffffu;
            v = __reduce_min_sync(0xffffffffu, v);
            if (lane == 0) s_minv = v;
        }
        __syncthreads();
        const u32 m = s_minv;
        const int slot = j & 1;
        if (tmin == m) atomicMin(&s_tid[slot], t);
        if (t == 0) s_tid[slot ^ 1] = 0x7fffffff;
        __syncthreads();
        if (t == s_tid[slot]) {
            bool found = false;
#pragma unroll
            for (int g = 0; g < 4; g++) {
                if (!found && gmin[g] == m) {
                    bool f2 = false;
#pragma unroll
                    for (int k = 0; k < 8; k++) {
                        if (!f2 && u[8 * g + k] == m) {
                            u[8 * g + k] = 0xffffffffu;
                            s_win[j] = p0 + 8 * g + k;
                            f2 = true;
                        }
                    }
                    u32 nm = u[8 * g];
#pragma unroll
                    for (int k = 1; k < 8; k++) nm = min(nm, u[8 * g + k]);
                    gmin[g] = nm;
                    found = true;
                }
            }
            tmin = min(min(gmin[0], gmin[1]), min(gmin[2], gmin[3]));
        }
    }

    __syncthreads();
    if (t < NB) {
        const int win = s_win[t];
        const float x = base[win], y = base[NN + win], z = base[2 * NN + win];
        const size_t r = (size_t)b * 1536 + (size_t)q * NB + t;
        float* o1 = out + r * 3;
        o1[0] = x; o1[1] = y; o1[2] = z;
        float* o2 = out + (r + 512) * 3;
        o2[0] = x; o2[1] = y; o2[2] = z;
    }
}

// ============================================================================
// Launch: fork a side stream for the anchor pipeline (fps50 -> count ->
// top4 -> knn) so it overlaps the full 512-iteration FPS on the main
// stream.  The branches write disjoint out regions and share no state.
// Streams/events are created fresh per call (no static guards) and not
// destroyed here: destroying a forked stream before the harness's
// EndCapture would invalidate the graph; they are host-side objects only.
// ============================================================================
extern "C" void kernel_launch(void* const* d_in, const int* in_sizes, int n_in,
                              void* d_out, int out_size)
{
    const float* pts = (const float*)d_in[0];
    float* out = (float*)d_out;

    cudaStream_t s2;
    cudaStreamCreateWithFlags(&s2, cudaStreamNonBlocking);
    cudaEvent_t e1, e2;
    cudaEventCreateWithFlags(&e1, cudaEventDisableTiming);
    cudaEventCreateWithFlags(&e2, cudaEventDisableTiming);

    cudaEventRecord(e1, 0);             // fork point on the main stream
    cudaStreamWaitEvent(s2, e1, 0);

    // side stream: anchor prefix + region pipeline (writes out rows 0..1023)
    fps_kernel<NANC, false><<<dim3(CSZ, BB), FT, 0, s2>>>(pts, out);
    count_kernel<<<dim3(NREG, BB), 256, 0, s2>>>(pts);
    top4_kernel<<<BB, 32, 0, s2>>>();
    knn_kernel<<<dim3(TOPK, BB), KT, 0, s2>>>(pts, out);
    cudaEventRecord(e2, s2);

    // main stream: full FPS (writes out rows 1024..1535), concurrent
    fps_kernel<NFPS, true><<<dim3(CSZ, BB), FT>>>(pts, out);

    cudaStreamWaitEvent(0, e2, 0);      // join
}